// round 13
// baseline (speedup 1.0000x reference)
#include <cuda_runtime.h>
#include <cstdint>

// PyramidROIAlign, warp-per-pool-point (R9 structure, champion) with
// write-through stores (__stwt) so the 100MB write-once output stream does
// NOT allocate in L2 and evict feature rows.
//   boxes: (2, 1000, 4) f32; p2: (2, 256, 256, 256) f32 NHWC
//   out:   (2, 1000, 7, 7, 256) f32
//
// KEY FACT (proved R6): for any normalized box h,w <= 1,
// clip(round(log2(sqrt(hw)/0.21875)),2,5) == 2 always -> only p2 sampled.
//
// Session law (R4/R7/R8/R11/R12): maximize (resident warps) x (batched
// loads/warp) = 64 x 8 at 32 regs, 128-thread CTAs (R12 showed 64-thr CTAs
// regress). 98000 points = 24500 blocks x 4 warps, exact.

#define BATCH   2
#define NROI    1000
#define POOLH   7
#define POOLW   7
#define NCH     256
#define NCH4    (NCH / 4)            // 64
#define POINTS  (POOLH * POOLW)      // 49
#define NPTS    (BATCH * NROI * POINTS)   // 98000
#define FH      256                  // p2 spatial size

__device__ __forceinline__ float4 lerp2(const float4 v00, const float4 v01,
                                        const float4 v10, const float4 v11,
                                        const float wx, const float wy)
{
    float4 r;
    float t, bo;
    t  = v00.x + wx * (v01.x - v00.x);
    bo = v10.x + wx * (v11.x - v10.x);
    r.x = t + wy * (bo - t);
    t  = v00.y + wx * (v01.y - v00.y);
    bo = v10.y + wx * (v11.y - v10.y);
    r.y = t + wy * (bo - t);
    t  = v00.z + wx * (v01.z - v00.z);
    bo = v10.z + wx * (v11.z - v10.z);
    r.z = t + wy * (bo - t);
    t  = v00.w + wx * (v01.w - v00.w);
    bo = v10.w + wx * (v11.w - v10.w);
    r.w = t + wy * (bo - t);
    return r;
}

__global__ __launch_bounds__(128, 16) void pyramid_roi_align_kernel(
    const float* __restrict__ boxes,
    const float* __restrict__ p2,
    float4* __restrict__ out)
{
    const int lane = threadIdx.x & 31;
    const int wrp  = threadIdx.x >> 5;
    const int pt   = blockIdx.x * 4 + wrp;    // 0..97999, exact

    // ---- warp-uniform param computation (registers only) ----
    const int roi = pt / POINTS;              // IMAD magic div
    const int ppt = pt - roi * POINTS;        // 0..48
    const int py  = ppt / POOLW;
    const int px  = ppt - py * POOLW;
    const int b   = roi >= NROI ? 1 : 0;

    const float4 bx = __ldg((const float4*)(boxes) + roi);
    const float y1 = bx.x, x1 = bx.y, y2 = bx.z, x2 = bx.w;
    const float h = y2 - y1;
    const float w = x2 - x1;

    // level == 2 always (proof in header): sample p2, H = W = 256.
    const float Hm1 = (float)(FH - 1);
    const float ty = (float)py * (1.0f / 6.0f);
    const float tx = (float)px * (1.0f / 6.0f);
    const float ysf = (y1 + h * ty) * Hm1;
    const float xsf = (x1 + w * tx) * Hm1;

    const float y0f = floorf(ysf);
    const float x0f = floorf(xsf);
    const float wy = ysf - y0f;   // weights from UNCLAMPED floor (matches ref)
    const float wx = xsf - x0f;

    const int y0  = min(max((int)y0f, 0), FH - 1);
    const int y1i = min(max((int)y0f + 1, 0), FH - 1);
    const int x0  = min(max((int)x0f, 0), FH - 1);
    const int x1i = min(max((int)x0f + 1, 0), FH - 1);

    // NHWC float4 view: p2_4[((b*256 + y)*256 + x)*64 + c]
    const float4* __restrict__ f4 = (const float4*)p2;
    const int rowb0 = (b * FH + y0)  * FH;
    const int rowb1 = (b * FH + y1i) * FH;
    const float4* __restrict__ q00 = f4 + (rowb0 + x0 ) * NCH4 + lane;
    const float4* __restrict__ q01 = f4 + (rowb0 + x1i) * NCH4 + lane;
    const float4* __restrict__ q10 = f4 + (rowb1 + x0 ) * NCH4 + lane;
    const float4* __restrict__ q11 = f4 + (rowb1 + x1i) * NCH4 + lane;

    // ---- 8 batched independent gathers (channels lane, lane+32) ----
    const float4 a00 = __ldg(q00);
    const float4 a01 = __ldg(q01);
    const float4 a10 = __ldg(q10);
    const float4 a11 = __ldg(q11);
    const float4 b00 = __ldg(q00 + 32);
    const float4 b01 = __ldg(q01 + 32);
    const float4 b10 = __ldg(q10 + 32);
    const float4 b11 = __ldg(q11 + 32);

    const float4 ra = lerp2(a00, a01, a10, a11, wx, wy);
    const float4 rb = lerp2(b00, b01, b10, b11, wx, wy);

    // Write-through stores: don't allocate the 100MB output in L2;
    // preserve L2 capacity for feature-row reuse.
    float4* __restrict__ o = out + (long long)pt * NCH4 + lane;
    __stwt(o,      ra);
    __stwt(o + 32, rb);
}

extern "C" void kernel_launch(void* const* d_in, const int* in_sizes, int n_in,
                              void* d_out, int out_size)
{
    const float* boxes = (const float*)d_in[0];
    const float* p2    = (const float*)d_in[1];
    float4* out = (float4*)d_out;

    pyramid_roi_align_kernel<<<NPTS / 4, 128>>>(boxes, p2, out);  // 24500 blocks
}

// round 14
// speedup vs baseline: 1.2318x; 1.2318x over previous
#include <cuda_runtime.h>
#include <cstdint>

// PyramidROIAlign — FINAL (champion, R9 structure).
//   boxes: (2, 1000, 4) f32; p2: (2, 256, 256, 256) f32 NHWC
//   out:   (2, 1000, 7, 7, 256) f32
//
// KEY FACT (proved R6): for any normalized box h,w <= 1,
// clip(round(log2(sqrt(hw)/0.21875)),2,5) == 2 always -> only p2 is ever
// sampled; p3/p4/p5 contribute nothing.
//
// Converged design (13 rounds of ncu-driven search):
//  - warp-per-pool-point, flat grid: 98000 points = 24500 blocks x 4 warps
//  - warp-uniform param math in registers (no smem/scratch/syncs)
//  - 8 batched independent LDG.128 per warp (4 corners x 2 channel halves)
//  - 32 regs -> 64 warps/SM: maximizes (resident warps) x (loads in flight)
//  - 128-thread CTAs: optimal retire granularity (256 and 64 both regress)
//  - __stcs evict-first stores (__stwt write-through regresses badly)

#define BATCH   2
#define NROI    1000
#define POOLH   7
#define POOLW   7
#define NCH     256
#define NCH4    (NCH / 4)            // 64
#define POINTS  (POOLH * POOLW)      // 49
#define NPTS    (BATCH * NROI * POINTS)   // 98000
#define FH      256                  // p2 spatial size

__device__ __forceinline__ float4 lerp2(const float4 v00, const float4 v01,
                                        const float4 v10, const float4 v11,
                                        const float wx, const float wy)
{
    float4 r;
    float t, bo;
    t  = v00.x + wx * (v01.x - v00.x);
    bo = v10.x + wx * (v11.x - v10.x);
    r.x = t + wy * (bo - t);
    t  = v00.y + wx * (v01.y - v00.y);
    bo = v10.y + wx * (v11.y - v10.y);
    r.y = t + wy * (bo - t);
    t  = v00.z + wx * (v01.z - v00.z);
    bo = v10.z + wx * (v11.z - v10.z);
    r.z = t + wy * (bo - t);
    t  = v00.w + wx * (v01.w - v00.w);
    bo = v10.w + wx * (v11.w - v10.w);
    r.w = t + wy * (bo - t);
    return r;
}

__global__ __launch_bounds__(128, 16) void pyramid_roi_align_kernel(
    const float* __restrict__ boxes,
    const float* __restrict__ p2,
    float4* __restrict__ out)
{
    const int lane = threadIdx.x & 31;
    const int wrp  = threadIdx.x >> 5;
    const int pt   = blockIdx.x * 4 + wrp;    // 0..97999, exact

    // ---- warp-uniform param computation (registers only) ----
    const int roi = pt / POINTS;              // IMAD magic div
    const int ppt = pt - roi * POINTS;        // 0..48
    const int py  = ppt / POOLW;
    const int px  = ppt - py * POOLW;
    const int b   = roi >= NROI ? 1 : 0;

    const float4 bx = __ldg((const float4*)(boxes) + roi);
    const float y1 = bx.x, x1 = bx.y, y2 = bx.z, x2 = bx.w;
    const float h = y2 - y1;
    const float w = x2 - x1;

    // level == 2 always (proof in header): sample p2, H = W = 256.
    const float Hm1 = (float)(FH - 1);
    const float ty = (float)py * (1.0f / 6.0f);
    const float tx = (float)px * (1.0f / 6.0f);
    const float ysf = (y1 + h * ty) * Hm1;
    const float xsf = (x1 + w * tx) * Hm1;

    const float y0f = floorf(ysf);
    const float x0f = floorf(xsf);
    const float wy = ysf - y0f;   // weights from UNCLAMPED floor (matches ref)
    const float wx = xsf - x0f;

    const int y0  = min(max((int)y0f, 0), FH - 1);
    const int y1i = min(max((int)y0f + 1, 0), FH - 1);
    const int x0  = min(max((int)x0f, 0), FH - 1);
    const int x1i = min(max((int)x0f + 1, 0), FH - 1);

    // NHWC float4 view: p2_4[((b*256 + y)*256 + x)*64 + c]
    const float4* __restrict__ f4 = (const float4*)p2;
    const int rowb0 = (b * FH + y0)  * FH;
    const int rowb1 = (b * FH + y1i) * FH;
    const float4* __restrict__ q00 = f4 + (rowb0 + x0 ) * NCH4 + lane;
    const float4* __restrict__ q01 = f4 + (rowb0 + x1i) * NCH4 + lane;
    const float4* __restrict__ q10 = f4 + (rowb1 + x0 ) * NCH4 + lane;
    const float4* __restrict__ q11 = f4 + (rowb1 + x1i) * NCH4 + lane;

    // ---- 8 batched independent gathers (channels lane, lane+32) ----
    const float4 a00 = __ldg(q00);
    const float4 a01 = __ldg(q01);
    const float4 a10 = __ldg(q10);
    const float4 a11 = __ldg(q11);
    const float4 b00 = __ldg(q00 + 32);
    const float4 b01 = __ldg(q01 + 32);
    const float4 b10 = __ldg(q10 + 32);
    const float4 b11 = __ldg(q11 + 32);

    const float4 ra = lerp2(a00, a01, a10, a11, wx, wy);
    const float4 rb = lerp2(b00, b01, b10, b11, wx, wy);

    // Evict-first streaming stores (keep L2 capacity for feature reads).
    float4* __restrict__ o = out + (long long)pt * NCH4 + lane;
    __stcs(o,      ra);
    __stcs(o + 32, rb);
}

extern "C" void kernel_launch(void* const* d_in, const int* in_sizes, int n_in,
                              void* d_out, int out_size)
{
    const float* boxes = (const float*)d_in[0];
    const float* p2    = (const float*)d_in[1];
    float4* out = (float4*)d_out;

    pyramid_roi_align_kernel<<<NPTS / 4, 128>>>(boxes, p2, out);  // 24500 blocks
}

// round 15
// speedup vs baseline: 1.2740x; 1.0342x over previous
#include <cuda_runtime.h>
#include <cstdint>

// PyramidROIAlign — FINAL champion (converged after 14 ncu-driven rounds).
//   boxes: (2, 1000, 4) f32; p2: (2, 256, 256, 256) f32 NHWC
//   out:   (2, 1000, 7, 7, 256) f32
//
// KEY FACT (proved R6): for any normalized box h,w <= 1,
// clip(round(log2(sqrt(max(h*w,1e-12))/0.21875)), 2, 5) == 2 ALWAYS
// (level 3 would need sqrt(hw) >= 1.24 — impossible). Only p2 is sampled;
// p3/p4/p5 contribute nothing.
//
// Converged design laws (each alternative tested and regressed):
//  - warp-per-pool-point, flat grid: 98000 points = 24500 blocks x 4 warps
//  - warp-uniform param math in registers (no smem/scratch/syncs)
//  - 8 batched independent LDG.128 per warp (4 corners x 2 channel halves)
//  - 32 regs -> 64 warps/SM: (resident warps) x (batched loads) maximized
//    at the register-file capacity point; wider loads or 2-pt batching cost
//    registers and lose (R8/R11), serial loops lose (R7)
//  - 128-thread CTAs: retire-granularity optimum (256 and 64 both regress)
//  - __stcs evict-first stores (__stwt write-through regresses 34% via LSU
//    write-path occupancy)

#define BATCH   2
#define NROI    1000
#define POOLH   7
#define POOLW   7
#define NCH     256
#define NCH4    (NCH / 4)            // 64
#define POINTS  (POOLH * POOLW)      // 49
#define NPTS    (BATCH * NROI * POINTS)   // 98000
#define FH      256                  // p2 spatial size

__device__ __forceinline__ float4 lerp2(const float4 v00, const float4 v01,
                                        const float4 v10, const float4 v11,
                                        const float wx, const float wy)
{
    float4 r;
    float t, bo;
    t  = v00.x + wx * (v01.x - v00.x);
    bo = v10.x + wx * (v11.x - v10.x);
    r.x = t + wy * (bo - t);
    t  = v00.y + wx * (v01.y - v00.y);
    bo = v10.y + wx * (v11.y - v10.y);
    r.y = t + wy * (bo - t);
    t  = v00.z + wx * (v01.z - v00.z);
    bo = v10.z + wx * (v11.z - v10.z);
    r.z = t + wy * (bo - t);
    t  = v00.w + wx * (v01.w - v00.w);
    bo = v10.w + wx * (v11.w - v10.w);
    r.w = t + wy * (bo - t);
    return r;
}

__global__ __launch_bounds__(128, 16) void pyramid_roi_align_kernel(
    const float* __restrict__ boxes,
    const float* __restrict__ p2,
    float4* __restrict__ out)
{
    const int lane = threadIdx.x & 31;
    const int wrp  = threadIdx.x >> 5;
    const int pt   = blockIdx.x * 4 + wrp;    // 0..97999, exact

    // ---- warp-uniform param computation (registers only) ----
    const int roi = pt / POINTS;              // IMAD magic div
    const int ppt = pt - roi * POINTS;        // 0..48
    const int py  = ppt / POOLW;
    const int px  = ppt - py * POOLW;
    const int b   = roi >= NROI ? 1 : 0;

    const float4 bx = __ldg((const float4*)(boxes) + roi);
    const float y1 = bx.x, x1 = bx.y, y2 = bx.z, x2 = bx.w;
    const float h = y2 - y1;
    const float w = x2 - x1;

    // level == 2 always (proof in header): sample p2, H = W = 256.
    const float Hm1 = (float)(FH - 1);
    const float ty = (float)py * (1.0f / 6.0f);
    const float tx = (float)px * (1.0f / 6.0f);
    const float ysf = (y1 + h * ty) * Hm1;
    const float xsf = (x1 + w * tx) * Hm1;

    const float y0f = floorf(ysf);
    const float x0f = floorf(xsf);
    const float wy = ysf - y0f;   // weights from UNCLAMPED floor (matches ref)
    const float wx = xsf - x0f;

    const int y0  = min(max((int)y0f, 0), FH - 1);
    const int y1i = min(max((int)y0f + 1, 0), FH - 1);
    const int x0  = min(max((int)x0f, 0), FH - 1);
    const int x1i = min(max((int)x0f + 1, 0), FH - 1);

    // NHWC float4 view: p2_4[((b*256 + y)*256 + x)*64 + c]
    const float4* __restrict__ f4 = (const float4*)p2;
    const int rowb0 = (b * FH + y0)  * FH;
    const int rowb1 = (b * FH + y1i) * FH;
    const float4* __restrict__ q00 = f4 + (rowb0 + x0 ) * NCH4 + lane;
    const float4* __restrict__ q01 = f4 + (rowb0 + x1i) * NCH4 + lane;
    const float4* __restrict__ q10 = f4 + (rowb1 + x0 ) * NCH4 + lane;
    const float4* __restrict__ q11 = f4 + (rowb1 + x1i) * NCH4 + lane;

    // ---- 8 batched independent gathers (channels lane, lane+32) ----
    const float4 a00 = __ldg(q00);
    const float4 a01 = __ldg(q01);
    const float4 a10 = __ldg(q10);
    const float4 a11 = __ldg(q11);
    const float4 b00 = __ldg(q00 + 32);
    const float4 b01 = __ldg(q01 + 32);
    const float4 b10 = __ldg(q10 + 32);
    const float4 b11 = __ldg(q11 + 32);

    const float4 ra = lerp2(a00, a01, a10, a11, wx, wy);
    const float4 rb = lerp2(b00, b01, b10, b11, wx, wy);

    // Evict-first streaming stores (keep L2 capacity for feature reads).
    float4* __restrict__ o = out + (long long)pt * NCH4 + lane;
    __stcs(o,      ra);
    __stcs(o + 32, rb);
}

extern "C" void kernel_launch(void* const* d_in, const int* in_sizes, int n_in,
                              void* d_out, int out_size)
{
    const float* boxes = (const float*)d_in[0];
    const float* p2    = (const float*)d_in[1];
    float4* out = (float4*)d_out;

    pyramid_roi_align_kernel<<<NPTS / 4, 128>>>(boxes, p2, out);  // 24500 blocks
}